// round 5
// baseline (speedup 1.0000x reference)
#include <cuda_runtime.h>
#include <math.h>
#include <stdint.h>

// ---------------- problem constants ----------------
#define BATCH   2
#define HT      64
#define WT      64
#define CDIM    768
#define WIN     14
#define NWIN1   5
#define NWINB   25
#define NW      50
#define HW      196
#define NHEAD   12
#define HD      64
#define MLPD    3072
#define TOKW    (NW*HW)        // 9800
#define TOKG    (BATCH*HT*WT)  // 8192
#define EPS     1e-5f

// ---------------- scratch ----------------
__device__ float g_xw  [TOKW * CDIM];
__device__ float g_qkv [TOKW * 3 * CDIM];
__device__ float g_attn[TOKW * CDIM];
__device__ float g_x2  [TOKG * CDIM];
__device__ float g_xn2 [TOKG * CDIM];
__device__ float g_hid [TOKG * MLPD];

// ---------------- helpers ----------------
__device__ __forceinline__ void win_map(int row, int& gidx, bool& valid) {
    int n  = row / HW, t = row % HW;
    int bb = n / NWINB, nw = n % NWINB;
    int wh = nw / NWIN1, ww = nw % NWIN1;
    int ii = t / WIN,    jj = t % WIN;
    int gh = wh * WIN + ii, gw = ww * WIN + jj;
    valid = (gh < HT) && (gw < WT);
    gidx  = (bb * HT + gh) * WT + gw;
}

__device__ __forceinline__ float to_tf32(float x) {
    uint32_t u;
    asm("cvt.rna.tf32.f32 %0, %1;" : "=r"(u) : "f"(x));
    return __uint_as_float(u);
}
__device__ __forceinline__ uint32_t smem_u32(const void* p) {
    return (uint32_t)__cvta_generic_to_shared(p);
}
__device__ __forceinline__ void cp16(uint32_t dst, const void* src, bool v) {
    int sz = v ? 16 : 0;
    asm volatile("cp.async.cg.shared.global [%0], [%1], 16, %2;\n"
                 :: "r"(dst), "l"(src), "r"(sz));
}
__device__ __forceinline__ void ldsm4(uint32_t& r0, uint32_t& r1,
                                      uint32_t& r2, uint32_t& r3, uint32_t a) {
    asm volatile("ldmatrix.sync.aligned.m8n8.x4.shared.b16 {%0,%1,%2,%3}, [%4];"
                 : "=r"(r0), "=r"(r1), "=r"(r2), "=r"(r3) : "r"(a));
}

// ---------------- LayerNorm kernels ----------------
__global__ __launch_bounds__(256) void ln_win_kernel(
    const float* __restrict__ x, const float* __restrict__ g,
    const float* __restrict__ b)
{
    int row = blockIdx.x;
    int tid = threadIdx.x;
    float* orow = g_xw + (size_t)row * CDIM;

    int gidx; bool valid;
    win_map(row, gidx, valid);
    if (!valid) {
        for (int c = tid; c < CDIM; c += 256) orow[c] = 0.f;
        return;
    }
    const float* xr = x + (size_t)gidx * CDIM;
    float v[3]; float s = 0.f, sq = 0.f;
    #pragma unroll
    for (int u = 0; u < 3; u++) {
        v[u] = xr[tid + u * 256];
        s += v[u]; sq += v[u] * v[u];
    }
    __shared__ float red[2][8];
    #pragma unroll
    for (int off = 16; off; off >>= 1) {
        s  += __shfl_xor_sync(~0u, s,  off);
        sq += __shfl_xor_sync(~0u, sq, off);
    }
    if ((tid & 31) == 0) { red[0][tid >> 5] = s; red[1][tid >> 5] = sq; }
    __syncthreads();
    if (tid < 32) {
        float a = (tid < 8) ? red[0][tid] : 0.f;
        float c = (tid < 8) ? red[1][tid] : 0.f;
        #pragma unroll
        for (int off = 4; off; off >>= 1) {
            a += __shfl_xor_sync(~0u, a, off);
            c += __shfl_xor_sync(~0u, c, off);
        }
        if (tid == 0) { red[0][0] = a; red[1][0] = c; }
    }
    __syncthreads();
    float mean = red[0][0] * (1.f / CDIM);
    float var  = red[1][0] * (1.f / CDIM) - mean * mean;
    float rstd = rsqrtf(var + EPS);
    #pragma unroll
    for (int u = 0; u < 3; u++) {
        int c = tid + u * 256;
        orow[c] = to_tf32((v[u] - mean) * rstd * g[c] + b[c]);
    }
}

__global__ __launch_bounds__(256) void ln2_kernel(
    const float* __restrict__ g, const float* __restrict__ b)
{
    int row = blockIdx.x;
    int tid = threadIdx.x;
    const float* xr = g_x2 + (size_t)row * CDIM;
    float* orow = g_xn2 + (size_t)row * CDIM;
    float v[3]; float s = 0.f, sq = 0.f;
    #pragma unroll
    for (int u = 0; u < 3; u++) {
        v[u] = xr[tid + u * 256];
        s += v[u]; sq += v[u] * v[u];
    }
    __shared__ float red[2][8];
    #pragma unroll
    for (int off = 16; off; off >>= 1) {
        s  += __shfl_xor_sync(~0u, s,  off);
        sq += __shfl_xor_sync(~0u, sq, off);
    }
    if ((tid & 31) == 0) { red[0][tid >> 5] = s; red[1][tid >> 5] = sq; }
    __syncthreads();
    if (tid < 32) {
        float a = (tid < 8) ? red[0][tid] : 0.f;
        float c = (tid < 8) ? red[1][tid] : 0.f;
        #pragma unroll
        for (int off = 4; off; off >>= 1) {
            a += __shfl_xor_sync(~0u, a, off);
            c += __shfl_xor_sync(~0u, c, off);
        }
        if (tid == 0) { red[0][0] = a; red[1][0] = c; }
    }
    __syncthreads();
    float mean = red[0][0] * (1.f / CDIM);
    float var  = red[1][0] * (1.f / CDIM) - mean * mean;
    float rstd = rsqrtf(var + EPS);
    #pragma unroll
    for (int u = 0; u < 3; u++) {
        int c = tid + u * 256;
        orow[c] = to_tf32((v[u] - mean) * rstd * g[c] + b[c]);
    }
}

// ---------------- TF32 GEMM: 3-stage cp.async, 1 sync per 32-k tile --------
// C[M,N] = A[M,K] @ B[K,N] + bias
// mode 0: plain   1: exact GELU(round)   2: += res[row]   3: unpartition + xin
#define KTILE   32
#define STAGES  3
#define AST     36
#define BST     136
#define A_STAGE (128 * AST)      // floats
#define B_STAGE (KTILE * BST)    // floats
#define GSMEM   (STAGES * (A_STAGE + B_STAGE) * 4)

__global__ __launch_bounds__(256, 2) void tgemm_kernel(
    const float* __restrict__ A, const float* __restrict__ Bm,
    const float* __restrict__ bias, const float* __restrict__ res,
    const float* __restrict__ xin, float* __restrict__ Cc,
    int M, int N, int K, int mode)
{
    extern __shared__ float sh[];
    float* AsS = sh;                       // [STAGES][128][AST]
    float* BsS = sh + STAGES * A_STAGE;    // [STAGES][KTILE][BST]

    int tid  = threadIdx.x;
    int warp = tid >> 5, lane = tid & 31;
    int wm = warp >> 2, wn = warp & 3;     // 2x4 warps, warp tile 64x32
    int gq = lane >> 2, tr = lane & 3;
    int bm = blockIdx.y * 128, bn = blockIdx.x * 128;

    // A staging: row tid>>1, 16 floats at (tid&1)*16
    int arow = tid >> 1;
    int acol = (tid & 1) * 16;
    int arow_g = bm + arow;
    bool aval = arow_g < M;
    const float* Ag = A + (size_t)(aval ? arow_g : (M - 1)) * K + acol;
    uint32_t as_st = smem_u32(AsS + arow * AST + acol);

    // B staging: row tid>>3 (0..31), 16 floats at (tid&7)*16
    int brow = tid >> 3;
    int bcolf = (tid & 7) * 16;
    const float* Bg = Bm + (size_t)brow * N + bn + bcolf;
    uint32_t bs_st = smem_u32(BsS + brow * BST + bcolf);

    uint32_t as_base = smem_u32(AsS);
    int a_r = lane & 15;
    int a_c = (lane >> 4) << 2;

    float acc[4][4][4];
    #pragma unroll
    for (int mi = 0; mi < 4; mi++)
        #pragma unroll
        for (int ni = 0; ni < 4; ni++)
            #pragma unroll
            for (int r = 0; r < 4; r++) acc[mi][ni][r] = 0.f;

    int T = K / KTILE;

    // fill stage s with k-tile t
    #define FILL(t, s) do {                                                  \
        const float* ag_ = Ag + (t) * KTILE;                                 \
        uint32_t ad_ = as_st + (s) * (A_STAGE * 4);                          \
        cp16(ad_,      ag_,      aval); cp16(ad_ + 16, ag_ + 4,  aval);      \
        cp16(ad_ + 32, ag_ + 8,  aval); cp16(ad_ + 48, ag_ + 12, aval);      \
        const float* bg_ = Bg + (size_t)(t) * KTILE * N;                     \
        uint32_t bd_ = bs_st + (s) * (B_STAGE * 4);                          \
        cp16(bd_,      bg_,               true);                             \
        cp16(bd_ + 16, bg_ + 4,           true);                             \
        cp16(bd_ + 32, bg_ + 8,           true);                             \
        cp16(bd_ + 48, bg_ + 12,          true);                             \
        asm volatile("cp.async.commit_group;\n");                            \
    } while (0)

    FILL(0, 0);
    FILL(1, 1);

    int s = 0;
    for (int t = 0; t < T; t++) {
        if (t + 1 < T) asm volatile("cp.async.wait_group 1;\n");
        else           asm volatile("cp.async.wait_group 0;\n");
        __syncthreads();
        if (t + 2 < T) {
            int sf = (s == 0) ? 2 : s - 1;   // (t+2) % 3
            FILL(t + 2, sf);
        }

        uint32_t ab = as_base + s * (A_STAGE * 4);
        const float* bsp = BsS + s * B_STAGE + wn * 32 + gq;

        #pragma unroll
        for (int kk = 0; kk < KTILE; kk += 8) {
            uint32_t af[4][4], bf[4][2];
            #pragma unroll
            for (int mi = 0; mi < 4; mi++) {
                uint32_t addr = ab +
                    (((wm * 64 + mi * 16 + a_r) * AST) + kk + a_c) * 4;
                ldsm4(af[mi][0], af[mi][1], af[mi][2], af[mi][3], addr);
            }
            const float* br0 = bsp + (kk + tr) * BST;
            const float* br1 = br0 + 4 * BST;
            #pragma unroll
            for (int ni = 0; ni < 4; ni++) {
                bf[ni][0] = __float_as_uint(br0[ni * 8]);
                bf[ni][1] = __float_as_uint(br1[ni * 8]);
            }
            #pragma unroll
            for (int mi = 0; mi < 4; mi++)
                #pragma unroll
                for (int ni = 0; ni < 4; ni++) {
                    asm volatile(
                        "mma.sync.aligned.m16n8k8.row.col.f32.tf32.tf32.f32 "
                        "{%0,%1,%2,%3}, {%4,%5,%6,%7}, {%8,%9}, {%0,%1,%2,%3};\n"
                        : "+f"(acc[mi][ni][0]), "+f"(acc[mi][ni][1]),
                          "+f"(acc[mi][ni][2]), "+f"(acc[mi][ni][3])
                        : "r"(af[mi][0]), "r"(af[mi][1]),
                          "r"(af[mi][2]), "r"(af[mi][3]),
                          "r"(bf[ni][0]), "r"(bf[ni][1]));
                }
        }
        s = (s == 2) ? 0 : s + 1;
    }
    #undef FILL

    // ---------------- epilogue ----------------
    #pragma unroll
    for (int mi = 0; mi < 4; mi++) {
        int rbase = bm + wm * 64 + mi * 16 + gq;
        #pragma unroll
        for (int h = 0; h < 2; h++) {
            int row = rbase + 8 * h;
            if (row >= M) continue;
            int gidx = 0; bool valid = true;
            if (mode == 3) {
                win_map(row, gidx, valid);
                if (!valid) continue;
            }
            #pragma unroll
            for (int ni = 0; ni < 4; ni++) {
                int col = bn + wn * 32 + ni * 8 + tr * 2;
                float v0 = acc[mi][ni][2 * h]     + bias[col];
                float v1 = acc[mi][ni][2 * h + 1] + bias[col + 1];
                if (mode == 1) {
                    v0 = 0.5f * v0 * (1.f + erff(v0 * 0.70710678118654752f));
                    v1 = 0.5f * v1 * (1.f + erff(v1 * 0.70710678118654752f));
                    Cc[(size_t)row * N + col]     = to_tf32(v0);
                    Cc[(size_t)row * N + col + 1] = to_tf32(v1);
                } else if (mode == 2) {
                    Cc[(size_t)row * N + col]     = v0 + res[(size_t)row * N + col];
                    Cc[(size_t)row * N + col + 1] = v1 + res[(size_t)row * N + col + 1];
                } else if (mode == 3) {
                    Cc[(size_t)gidx * N + col]     = v0 + xin[(size_t)gidx * N + col];
                    Cc[(size_t)gidx * N + col + 1] = v1 + xin[(size_t)gidx * N + col + 1];
                } else {
                    Cc[(size_t)row * N + col]     = v0;
                    Cc[(size_t)row * N + col + 1] = v1;
                }
            }
        }
    }
}

// ---------------- fused window attention (conflict-free, vectorized) --------
#define KVS 68
#define ATTN_SMEM_FLOATS (HW*KVS*2 + 27*KVS*2 + 8*KVS + 8*28 + 8*200)

__global__ __launch_bounds__(256) void attn_kernel(
    const float* __restrict__ rel_h, const float* __restrict__ rel_w)
{
    extern __shared__ float sm[];
    float* ks = sm;                   // [196][68]
    float* vs = ks + HW * KVS;        // [196][68]
    float* rh = vs + HW * KVS;        // [27][68]
    float* rw = rh + 27 * KVS;        // [27][68]
    float* qs = rw + 27 * KVS;        // [8][68]
    float* bs = qs + 8 * KVS;         // [8][28]
    float* ps = bs + 8 * 28;          // [8][200]

    int w0   = blockIdx.x;
    int head = blockIdx.y;
    int tid  = threadIdx.x;
    int warp = tid >> 5, lane = tid & 31;

    const float* qkv_base = g_qkv + (size_t)w0 * HW * (3 * CDIM) + head * HD;
    for (int idx = tid; idx < HW * HD; idx += 256) {
        int kt = idx >> 6, d = idx & 63;
        const float* src = qkv_base + (size_t)kt * (3 * CDIM);
        ks[kt * KVS + d] = src[CDIM + d];
        vs[kt * KVS + d] = src[2 * CDIM + d];
    }
    for (int idx = tid; idx < 27 * HD; idx += 256) {
        int r = idx >> 6, d = idx & 63;
        rh[r * KVS + d] = rel_h[idx];
        rw[r * KVS + d] = rel_w[idx];
    }
    __syncthreads();

    int d0 = lane * 2;

    for (int r = warp; r < HW; r += 8) {
        size_t row = (size_t)w0 * HW + r;
        const float* qp = g_qkv + row * (3 * CDIM) + head * HD;
        qs[warp * KVS + lane]      = qp[lane];
        qs[warp * KVS + lane + 32] = qp[lane + 32];
        __syncwarp();

        int hq = r / WIN, wq = r % WIN;
        if (lane < 28) {
            const float* tab; int o;
            if (lane < 14) { tab = rh; o = (hq - lane + (WIN - 1)) * KVS; }
            else           { tab = rw; o = (wq - (lane - 14) + (WIN - 1)) * KVS; }
            float sacc = 0.f;
            #pragma unroll
            for (int d = 0; d < HD; d += 4) {
                float4 q4 = *(const float4*)&qs[warp * KVS + d];
                float4 t4 = *(const float4*)&tab[o + d];
                sacc += q4.x * t4.x + q4.y * t4.y + q4.z * t4.z + q4.w * t4.w;
            }
            bs[warp * 28 + lane] = sacc;
        }
        __syncwarp();

        float sc[7] = {0.f, 0.f, 0.f, 0.f, 0.f, 0.f, 0.f};
        int keyc[7];
        #pragma unroll
        for (int si = 0; si < 7; si++) {
            int key = lane + 32 * si;
            keyc[si] = key < HW ? key : HW - 1;
        }
        #pragma unroll 4
        for (int d = 0; d < HD; d += 4) {
            float4 q4 = *(const float4*)&qs[warp * KVS + d];
            #pragma unroll
            for (int si = 0; si < 7; si++) {
                float4 k4 = *(const float4*)&ks[keyc[si] * KVS + d];
                sc[si] += q4.x * k4.x + q4.y * k4.y + q4.z * k4.z + q4.w * k4.w;
            }
        }
        float mx = -1e30f;
        #pragma unroll
        for (int si = 0; si < 7; si++) {
            int key = lane + 32 * si;
            if (key < HW) {
                sc[si] = sc[si] * 0.125f
                       + bs[warp * 28 + key / WIN]
                       + bs[warp * 28 + 14 + key % WIN];
                mx = fmaxf(mx, sc[si]);
            } else sc[si] = -1e30f;
        }
        #pragma unroll
        for (int off = 16; off; off >>= 1)
            mx = fmaxf(mx, __shfl_xor_sync(~0u, mx, off));
        float sum = 0.f;
        #pragma unroll
        for (int si = 0; si < 7; si++) {
            int key = lane + 32 * si;
            if (key < HW) { float e = __expf(sc[si] - mx); sc[si] = e; sum += e; }
            else sc[si] = 0.f;
        }
        #pragma unroll
        for (int off = 16; off; off >>= 1)
            sum += __shfl_xor_sync(~0u, sum, off);
        float inv = 1.f / sum;
        #pragma unroll
        for (int si = 0; si < 7; si++) {
            int key = lane + 32 * si;
            if (key < HW) ps[warp * 200 + key] = sc[si] * inv;
        }
        __syncwarp();

        float o0 = 0.f, o1 = 0.f;
        #pragma unroll 4
        for (int k2 = 0; k2 < HW; k2 += 4) {
            float4 p4 = *(const float4*)&ps[warp * 200 + k2];
            float2 v0 = *(const float2*)&vs[(k2 + 0) * KVS + d0];
            float2 v1 = *(const float2*)&vs[(k2 + 1) * KVS + d0];
            float2 v2 = *(const float2*)&vs[(k2 + 2) * KVS + d0];
            float2 v3 = *(const float2*)&vs[(k2 + 3) * KVS + d0];
            o0 = fmaf(p4.x, v0.x, o0); o1 = fmaf(p4.x, v0.y, o1);
            o0 = fmaf(p4.y, v1.x, o0); o1 = fmaf(p4.y, v1.y, o1);
            o0 = fmaf(p4.z, v2.x, o0); o1 = fmaf(p4.z, v2.y, o1);
            o0 = fmaf(p4.w, v3.x, o0); o1 = fmaf(p4.w, v3.y, o1);
        }
        float* op = g_attn + row * CDIM + head * HD;
        *(float2*)&op[d0] = make_float2(to_tf32(o0), to_tf32(o1));
        __syncwarp();
    }
}

// ---------------- launcher ----------------
extern "C" void kernel_launch(void* const* d_in, const int* in_sizes, int n_in,
                              void* d_out, int out_size)
{
    const float* x      = (const float*)d_in[0];
    const float* g1     = (const float*)d_in[1];
    const float* b1     = (const float*)d_in[2];
    const float* w_qkv  = (const float*)d_in[3];
    const float* b_qkv  = (const float*)d_in[4];
    const float* w_proj = (const float*)d_in[5];
    const float* b_proj = (const float*)d_in[6];
    const float* rel_h  = (const float*)d_in[7];
    const float* rel_w  = (const float*)d_in[8];
    const float* g2     = (const float*)d_in[9];
    const float* b2     = (const float*)d_in[10];
    const float* w1     = (const float*)d_in[11];
    const float* b1m    = (const float*)d_in[12];
    const float* w2     = (const float*)d_in[13];
    const float* b2m    = (const float*)d_in[14];
    float* out = (float*)d_out;

    float *p_xw, *p_qkv, *p_attn, *p_x2, *p_xn2, *p_hid;
    cudaGetSymbolAddress((void**)&p_xw,   g_xw);
    cudaGetSymbolAddress((void**)&p_qkv,  g_qkv);
    cudaGetSymbolAddress((void**)&p_attn, g_attn);
    cudaGetSymbolAddress((void**)&p_x2,   g_x2);
    cudaGetSymbolAddress((void**)&p_xn2,  g_xn2);
    cudaGetSymbolAddress((void**)&p_hid,  g_hid);

    static int attr_set = 0;
    if (!attr_set) {
        cudaFuncSetAttribute(attn_kernel,
            cudaFuncAttributeMaxDynamicSharedMemorySize,
            ATTN_SMEM_FLOATS * sizeof(float));
        cudaFuncSetAttribute(tgemm_kernel,
            cudaFuncAttributeMaxDynamicSharedMemorySize, GSMEM);
        attr_set = 1;
    }

    // 1) LN1 + window partition -> g_xw [9800, 768]
    ln_win_kernel<<<TOKW, 256>>>(x, g1, b1);

    // 2) QKV GEMM: [9800,768] @ [768,2304]
    {
        dim3 grid((3 * CDIM) / 128, (TOKW + 127) / 128);
        tgemm_kernel<<<grid, 256, GSMEM>>>(p_xw, w_qkv, b_qkv, nullptr, nullptr,
                                           p_qkv, TOKW, 3 * CDIM, CDIM, 0);
    }

    // 3) fused attention per (window, head)
    attn_kernel<<<dim3(NW, NHEAD), 256, ATTN_SMEM_FLOATS * sizeof(float)>>>(rel_h, rel_w);

    // 4) proj GEMM + window unpartition + residual -> g_x2 [8192, 768]
    {
        dim3 grid(CDIM / 128, (TOKW + 127) / 128);
        tgemm_kernel<<<grid, 256, GSMEM>>>(p_attn, w_proj, b_proj, nullptr, x,
                                           p_x2, TOKW, CDIM, CDIM, 3);
    }

    // 5) LN2 -> g_xn2
    ln2_kernel<<<TOKG, 256>>>(g2, b2);

    // 6) FC1 + GELU: [8192,768] @ [768,3072]
    {
        dim3 grid(MLPD / 128, TOKG / 128);
        tgemm_kernel<<<grid, 256, GSMEM>>>(p_xn2, w1, b1m, nullptr, nullptr,
                                           p_hid, TOKG, MLPD, CDIM, 1);
    }

    // 7) FC2 + residual: [8192,3072] @ [3072,768] -> out
    {
        dim3 grid(CDIM / 128, TOKG / 128);
        tgemm_kernel<<<grid, 256, GSMEM>>>(p_hid, w2, b2m, p_x2, nullptr,
                                           out, TOKG, CDIM, MLPD, 2);
    }
}

// round 6
// speedup vs baseline: 1.1536x; 1.1536x over previous
#include <cuda_runtime.h>
#include <math.h>
#include <stdint.h>

// ---------------- problem constants ----------------
#define BATCH   2
#define HT      64
#define WT      64
#define CDIM    768
#define WIN     14
#define NWIN1   5
#define NWINB   25
#define NW      50
#define HW      196
#define NHEAD   12
#define HD      64
#define MLPD    3072
#define TOKW    (NW*HW)        // 9800
#define TOKG    (BATCH*HT*WT)  // 8192
#define EPS     1e-5f

// ---------------- scratch ----------------
__device__ float g_xw  [TOKW * CDIM];
__device__ float g_qkv [TOKW * 3 * CDIM];
__device__ float g_attn[TOKW * CDIM];
__device__ float g_x2  [TOKG * CDIM];
__device__ float g_xn2 [TOKG * CDIM];
__device__ float g_hid [TOKG * MLPD];

// ---------------- helpers ----------------
__device__ __forceinline__ void win_map(int row, int& gidx, bool& valid) {
    int n  = row / HW, t = row % HW;
    int bb = n / NWINB, nw = n % NWINB;
    int wh = nw / NWIN1, ww = nw % NWIN1;
    int ii = t / WIN,    jj = t % WIN;
    int gh = wh * WIN + ii, gw = ww * WIN + jj;
    valid = (gh < HT) && (gw < WT);
    gidx  = (bb * HT + gh) * WT + gw;
}

__device__ __forceinline__ float to_tf32(float x) {
    uint32_t u;
    asm("cvt.rna.tf32.f32 %0, %1;" : "=r"(u) : "f"(x));
    return __uint_as_float(u);
}
__device__ __forceinline__ uint32_t smem_u32(const void* p) {
    return (uint32_t)__cvta_generic_to_shared(p);
}
__device__ __forceinline__ void cp16(uint32_t dst, const void* src, bool v) {
    int sz = v ? 16 : 0;
    asm volatile("cp.async.cg.shared.global [%0], [%1], 16, %2;\n"
                 :: "r"(dst), "l"(src), "r"(sz));
}
__device__ __forceinline__ void ldsm4(uint32_t& r0, uint32_t& r1,
                                      uint32_t& r2, uint32_t& r3, uint32_t a) {
    asm volatile("ldmatrix.sync.aligned.m8n8.x4.shared.b16 {%0,%1,%2,%3}, [%4];"
                 : "=r"(r0), "=r"(r1), "=r"(r2), "=r"(r3) : "r"(a));
}

// ---------------- LayerNorm kernels ----------------
__global__ __launch_bounds__(256) void ln_win_kernel(
    const float* __restrict__ x, const float* __restrict__ g,
    const float* __restrict__ b)
{
    int row = blockIdx.x;
    int tid = threadIdx.x;
    float* orow = g_xw + (size_t)row * CDIM;

    int gidx; bool valid;
    win_map(row, gidx, valid);
    if (!valid) {
        for (int c = tid; c < CDIM; c += 256) orow[c] = 0.f;
        return;
    }
    const float* xr = x + (size_t)gidx * CDIM;
    float v[3]; float s = 0.f, sq = 0.f;
    #pragma unroll
    for (int u = 0; u < 3; u++) {
        v[u] = xr[tid + u * 256];
        s += v[u]; sq += v[u] * v[u];
    }
    __shared__ float red[2][8];
    #pragma unroll
    for (int off = 16; off; off >>= 1) {
        s  += __shfl_xor_sync(~0u, s,  off);
        sq += __shfl_xor_sync(~0u, sq, off);
    }
    if ((tid & 31) == 0) { red[0][tid >> 5] = s; red[1][tid >> 5] = sq; }
    __syncthreads();
    if (tid < 32) {
        float a = (tid < 8) ? red[0][tid] : 0.f;
        float c = (tid < 8) ? red[1][tid] : 0.f;
        #pragma unroll
        for (int off = 4; off; off >>= 1) {
            a += __shfl_xor_sync(~0u, a, off);
            c += __shfl_xor_sync(~0u, c, off);
        }
        if (tid == 0) { red[0][0] = a; red[1][0] = c; }
    }
    __syncthreads();
    float mean = red[0][0] * (1.f / CDIM);
    float var  = red[1][0] * (1.f / CDIM) - mean * mean;
    float rstd = rsqrtf(var + EPS);
    #pragma unroll
    for (int u = 0; u < 3; u++) {
        int c = tid + u * 256;
        orow[c] = to_tf32((v[u] - mean) * rstd * g[c] + b[c]);
    }
}

__global__ __launch_bounds__(256) void ln2_kernel(
    const float* __restrict__ g, const float* __restrict__ b)
{
    int row = blockIdx.x;
    int tid = threadIdx.x;
    const float* xr = g_x2 + (size_t)row * CDIM;
    float* orow = g_xn2 + (size_t)row * CDIM;
    float v[3]; float s = 0.f, sq = 0.f;
    #pragma unroll
    for (int u = 0; u < 3; u++) {
        v[u] = xr[tid + u * 256];
        s += v[u]; sq += v[u] * v[u];
    }
    __shared__ float red[2][8];
    #pragma unroll
    for (int off = 16; off; off >>= 1) {
        s  += __shfl_xor_sync(~0u, s,  off);
        sq += __shfl_xor_sync(~0u, sq, off);
    }
    if ((tid & 31) == 0) { red[0][tid >> 5] = s; red[1][tid >> 5] = sq; }
    __syncthreads();
    if (tid < 32) {
        float a = (tid < 8) ? red[0][tid] : 0.f;
        float c = (tid < 8) ? red[1][tid] : 0.f;
        #pragma unroll
        for (int off = 4; off; off >>= 1) {
            a += __shfl_xor_sync(~0u, a, off);
            c += __shfl_xor_sync(~0u, c, off);
        }
        if (tid == 0) { red[0][0] = a; red[1][0] = c; }
    }
    __syncthreads();
    float mean = red[0][0] * (1.f / CDIM);
    float var  = red[1][0] * (1.f / CDIM) - mean * mean;
    float rstd = rsqrtf(var + EPS);
    #pragma unroll
    for (int u = 0; u < 3; u++) {
        int c = tid + u * 256;
        orow[c] = to_tf32((v[u] - mean) * rstd * g[c] + b[c]);
    }
}

// ---------------- TF32 GEMM: ldmatrix frags, 3-stage A cp.async,
//                  2-buffer reg-staged B, ONE sync per 16-k tile ------------
// mode 0: plain   1: exact GELU(round)   2: += res[row]   3: unpartition + xin
#define ASTRIDE 20
#define A_STAGE (128 * ASTRIDE)            // floats per A stage
#define B_STAGE (128 * ASTRIDE)            // floats per B buffer ([n][k])
#define GSMEM   ((3 * A_STAGE + 2 * B_STAGE) * 4)

__global__ __launch_bounds__(256, 2) void tgemm_kernel(
    const float* __restrict__ A, const float* __restrict__ Bm,
    const float* __restrict__ bias, const float* __restrict__ res,
    const float* __restrict__ xin, float* __restrict__ Cc,
    int M, int N, int K, int mode)
{
    extern __shared__ float sh[];
    float* AsS = sh;                   // [3][128][ASTRIDE]  (m-major)
    float* BtS = sh + 3 * A_STAGE;     // [2][128][ASTRIDE]  (n-major, transposed)

    int tid  = threadIdx.x;
    int warp = tid >> 5, lane = tid & 31;
    int wm = warp >> 2, wn = warp & 3;      // 2x4 warps, warp tile 64x32
    int gq = lane >> 2, tr = lane & 3;
    int bm = blockIdx.y * 128, bn = blockIdx.x * 128;

    // A staging (cp.async): row tid>>1, 2x16B at cols (tid&1)*8, +4
    int arow = tid >> 1;
    int acol = (tid & 1) * 8;
    int arow_g = bm + arow;
    bool aval = arow_g < M;
    const float* Ag = A + (size_t)(aval ? arow_g : (M - 1)) * K + acol;
    uint32_t as_st = smem_u32(AsS + arow * ASTRIDE + acol);

    // B staging: thread covers n = tid&127, k rows blk..blk+7 (LDG coalesced)
    int bln = tid & 127;
    int blk = (tid >> 7) * 8;
    const float* Bg = Bm + (size_t)blk * N + bn + bln;
    float* bt_st = BtS + bln * ASTRIDE + blk;

    // ldmatrix lane offsets
    uint32_t as_base = smem_u32(AsS);
    uint32_t bt_base = smem_u32(BtS);
    int a_r = lane & 15;
    int a_c = (lane >> 4) << 2;
    int b_r = ((lane >> 4) << 3) + (lane & 7);
    int b_c = ((lane >> 3) & 1) << 2;

    float acc[4][4][4];
    #pragma unroll
    for (int mi = 0; mi < 4; mi++)
        #pragma unroll
        for (int ni = 0; ni < 4; ni++)
            #pragma unroll
            for (int r = 0; r < 4; r++) acc[mi][ni][r] = 0.f;

    int T = K / 16;
    float bregs[8];

    #define AFILL(t, s) do {                                    \
        const float* ag_ = Ag + (t) * 16;                       \
        uint32_t ad_ = as_st + (s) * (A_STAGE * 4);             \
        cp16(ad_,      ag_,     aval);                          \
        cp16(ad_ + 16, ag_ + 4, aval);                          \
        asm volatile("cp.async.commit_group;\n");               \
    } while (0)

    // prologue
    #pragma unroll
    for (int i = 0; i < 8; i++) bregs[i] = Bg[(size_t)i * N];
    AFILL(0, 0);
    AFILL(1, 1);

    int sA = 0;
    for (int t = 0; t < T; t++) {
        if (t + 1 < T) asm volatile("cp.async.wait_group 1;\n");
        else           asm volatile("cp.async.wait_group 0;\n");

        // STS B(t) into buffer t&1 (conflict-free: bank = 20n mod 32 distinct)
        int bcur = t & 1;
        float* bd = bt_st + bcur * B_STAGE;
        *(float4*)bd       = make_float4(bregs[0], bregs[1], bregs[2], bregs[3]);
        *(float4*)(bd + 4) = make_float4(bregs[4], bregs[5], bregs[6], bregs[7]);
        __syncthreads();

        // safe after barrier: stage (t+2)%3 was last read by compute(t-1)
        if (t + 2 < T) {
            int sf = (sA == 0) ? 2 : sA - 1;   // (t+2) % 3
            AFILL(t + 2, sf);
        }
        if (t + 1 < T) {
            const float* bg = Bg + (size_t)(t + 1) * 16 * N;
            #pragma unroll
            for (int i = 0; i < 8; i++) bregs[i] = bg[(size_t)i * N];
        }

        // compute: As[sA], Bt[bcur]
        uint32_t ab = as_base + sA * (A_STAGE * 4);
        uint32_t bb = bt_base + bcur * (B_STAGE * 4);
        #pragma unroll
        for (int kk = 0; kk < 16; kk += 8) {
            uint32_t af[4][4], bf[4][2];
            #pragma unroll
            for (int mi = 0; mi < 4; mi++) {
                uint32_t addr = ab +
                    (((wm * 64 + mi * 16 + a_r) * ASTRIDE) + kk + a_c) * 4;
                ldsm4(af[mi][0], af[mi][1], af[mi][2], af[mi][3], addr);
            }
            #pragma unroll
            for (int nh = 0; nh < 2; nh++) {
                uint32_t addr = bb +
                    (((wn * 32 + nh * 16 + b_r) * ASTRIDE) + kk + b_c) * 4;
                ldsm4(bf[2 * nh][0], bf[2 * nh][1],
                      bf[2 * nh + 1][0], bf[2 * nh + 1][1], addr);
            }
            #pragma unroll
            for (int mi = 0; mi < 4; mi++)
                #pragma unroll
                for (int ni = 0; ni < 4; ni++) {
                    asm volatile(
                        "mma.sync.aligned.m16n8k8.row.col.f32.tf32.tf32.f32 "
                        "{%0,%1,%2,%3}, {%4,%5,%6,%7}, {%8,%9}, {%0,%1,%2,%3};\n"
                        : "+f"(acc[mi][ni][0]), "+f"(acc[mi][ni][1]),
                          "+f"(acc[mi][ni][2]), "+f"(acc[mi][ni][3])
                        : "r"(af[mi][0]), "r"(af[mi][1]),
                          "r"(af[mi][2]), "r"(af[mi][3]),
                          "r"(bf[ni][0]), "r"(bf[ni][1]));
                }
        }
        sA = (sA == 2) ? 0 : sA + 1;
    }
    #undef AFILL

    // ---------------- epilogue ----------------
    #pragma unroll
    for (int mi = 0; mi < 4; mi++) {
        int rbase = bm + wm * 64 + mi * 16 + gq;
        #pragma unroll
        for (int h = 0; h < 2; h++) {
            int row = rbase + 8 * h;
            if (row >= M) continue;
            int gidx = 0; bool valid = true;
            if (mode == 3) {
                win_map(row, gidx, valid);
                if (!valid) continue;
            }
            #pragma unroll
            for (int ni = 0; ni < 4; ni++) {
                int col = bn + wn * 32 + ni * 8 + tr * 2;
                float v0 = acc[mi][ni][2 * h]     + bias[col];
                float v1 = acc[mi][ni][2 * h + 1] + bias[col + 1];
                if (mode == 1) {
                    v0 = 0.5f * v0 * (1.f + erff(v0 * 0.70710678118654752f));
                    v1 = 0.5f * v1 * (1.f + erff(v1 * 0.70710678118654752f));
                    Cc[(size_t)row * N + col]     = to_tf32(v0);
                    Cc[(size_t)row * N + col + 1] = to_tf32(v1);
                } else if (mode == 2) {
                    Cc[(size_t)row * N + col]     = v0 + res[(size_t)row * N + col];
                    Cc[(size_t)row * N + col + 1] = v1 + res[(size_t)row * N + col + 1];
                } else if (mode == 3) {
                    Cc[(size_t)gidx * N + col]     = v0 + xin[(size_t)gidx * N + col];
                    Cc[(size_t)gidx * N + col + 1] = v1 + xin[(size_t)gidx * N + col + 1];
                } else {
                    Cc[(size_t)row * N + col]     = v0;
                    Cc[(size_t)row * N + col + 1] = v1;
                }
            }
        }
    }
}

// ---------------- fused window attention (conflict-free, vectorized) --------
#define KVS 68
#define ATTN_SMEM_FLOATS (HW*KVS*2 + 27*KVS*2 + 8*KVS + 8*28 + 8*200)

__global__ __launch_bounds__(256) void attn_kernel(
    const float* __restrict__ rel_h, const float* __restrict__ rel_w)
{
    extern __shared__ float sm[];
    float* ks = sm;                   // [196][68]
    float* vs = ks + HW * KVS;        // [196][68]
    float* rh = vs + HW * KVS;        // [27][68]
    float* rw = rh + 27 * KVS;        // [27][68]
    float* qs = rw + 27 * KVS;        // [8][68]
    float* bs = qs + 8 * KVS;         // [8][28]
    float* ps = bs + 8 * 28;          // [8][200]

    int w0   = blockIdx.x;
    int head = blockIdx.y;
    int tid  = threadIdx.x;
    int warp = tid >> 5, lane = tid & 31;

    const float* qkv_base = g_qkv + (size_t)w0 * HW * (3 * CDIM) + head * HD;
    for (int idx = tid; idx < HW * HD; idx += 256) {
        int kt = idx >> 6, d = idx & 63;
        const float* src = qkv_base + (size_t)kt * (3 * CDIM);
        ks[kt * KVS + d] = src[CDIM + d];
        vs[kt * KVS + d] = src[2 * CDIM + d];
    }
    for (int idx = tid; idx < 27 * HD; idx += 256) {
        int r = idx >> 6, d = idx & 63;
        rh[r * KVS + d] = rel_h[idx];
        rw[r * KVS + d] = rel_w[idx];
    }
    __syncthreads();

    int d0 = lane * 2;

    for (int r = warp; r < HW; r += 8) {
        size_t row = (size_t)w0 * HW + r;
        const float* qp = g_qkv + row * (3 * CDIM) + head * HD;
        qs[warp * KVS + lane]      = qp[lane];
        qs[warp * KVS + lane + 32] = qp[lane + 32];
        __syncwarp();

        int hq = r / WIN, wq = r % WIN;
        if (lane < 28) {
            const float* tab; int o;
            if (lane < 14) { tab = rh; o = (hq - lane + (WIN - 1)) * KVS; }
            else           { tab = rw; o = (wq - (lane - 14) + (WIN - 1)) * KVS; }
            float sacc = 0.f;
            #pragma unroll
            for (int d = 0; d < HD; d += 4) {
                float4 q4 = *(const float4*)&qs[warp * KVS + d];
                float4 t4 = *(const float4*)&tab[o + d];
                sacc += q4.x * t4.x + q4.y * t4.y + q4.z * t4.z + q4.w * t4.w;
            }
            bs[warp * 28 + lane] = sacc;
        }
        __syncwarp();

        float sc[7] = {0.f, 0.f, 0.f, 0.f, 0.f, 0.f, 0.f};
        int keyc[7];
        #pragma unroll
        for (int si = 0; si < 7; si++) {
            int key = lane + 32 * si;
            keyc[si] = key < HW ? key : HW - 1;
        }
        #pragma unroll 4
        for (int d = 0; d < HD; d += 4) {
            float4 q4 = *(const float4*)&qs[warp * KVS + d];
            #pragma unroll
            for (int si = 0; si < 7; si++) {
                float4 k4 = *(const float4*)&ks[keyc[si] * KVS + d];
                sc[si] += q4.x * k4.x + q4.y * k4.y + q4.z * k4.z + q4.w * k4.w;
            }
        }
        float mx = -1e30f;
        #pragma unroll
        for (int si = 0; si < 7; si++) {
            int key = lane + 32 * si;
            if (key < HW) {
                sc[si] = sc[si] * 0.125f
                       + bs[warp * 28 + key / WIN]
                       + bs[warp * 28 + 14 + key % WIN];
                mx = fmaxf(mx, sc[si]);
            } else sc[si] = -1e30f;
        }
        #pragma unroll
        for (int off = 16; off; off >>= 1)
            mx = fmaxf(mx, __shfl_xor_sync(~0u, mx, off));
        float sum = 0.f;
        #pragma unroll
        for (int si = 0; si < 7; si++) {
            int key = lane + 32 * si;
            if (key < HW) { float e = __expf(sc[si] - mx); sc[si] = e; sum += e; }
            else sc[si] = 0.f;
        }
        #pragma unroll
        for (int off = 16; off; off >>= 1)
            sum += __shfl_xor_sync(~0u, sum, off);
        float inv = 1.f / sum;
        #pragma unroll
        for (int si = 0; si < 7; si++) {
            int key = lane + 32 * si;
            if (key < HW) ps[warp * 200 + key] = sc[si] * inv;
        }
        __syncwarp();

        float o0 = 0.f, o1 = 0.f;
        #pragma unroll 4
        for (int k2 = 0; k2 < HW; k2 += 4) {
            float4 p4 = *(const float4*)&ps[warp * 200 + k2];
            float2 v0 = *(const float2*)&vs[(k2 + 0) * KVS + d0];
            float2 v1 = *(const float2*)&vs[(k2 + 1) * KVS + d0];
            float2 v2 = *(const float2*)&vs[(k2 + 2) * KVS + d0];
            float2 v3 = *(const float2*)&vs[(k2 + 3) * KVS + d0];
            o0 = fmaf(p4.x, v0.x, o0); o1 = fmaf(p4.x, v0.y, o1);
            o0 = fmaf(p4.y, v1.x, o0); o1 = fmaf(p4.y, v1.y, o1);
            o0 = fmaf(p4.z, v2.x, o0); o1 = fmaf(p4.z, v2.y, o1);
            o0 = fmaf(p4.w, v3.x, o0); o1 = fmaf(p4.w, v3.y, o1);
        }
        float* op = g_attn + row * CDIM + head * HD;
        *(float2*)&op[d0] = make_float2(to_tf32(o0), to_tf32(o1));
        __syncwarp();
    }
}

// ---------------- launcher ----------------
extern "C" void kernel_launch(void* const* d_in, const int* in_sizes, int n_in,
                              void* d_out, int out_size)
{
    const float* x      = (const float*)d_in[0];
    const float* g1     = (const float*)d_in[1];
    const float* b1     = (const float*)d_in[2];
    const float* w_qkv  = (const float*)d_in[3];
    const float* b_qkv  = (const float*)d_in[4];
    const float* w_proj = (const float*)d_in[5];
    const float* b_proj = (const float*)d_in[6];
    const float* rel_h  = (const float*)d_in[7];
    const float* rel_w  = (const float*)d_in[8];
    const float* g2     = (const float*)d_in[9];
    const float* b2     = (const float*)d_in[10];
    const float* w1     = (const float*)d_in[11];
    const float* b1m    = (const float*)d_in[12];
    const float* w2     = (const float*)d_in[13];
    const float* b2m    = (const float*)d_in[14];
    float* out = (float*)d_out;

    float *p_xw, *p_qkv, *p_attn, *p_x2, *p_xn2, *p_hid;
    cudaGetSymbolAddress((void**)&p_xw,   g_xw);
    cudaGetSymbolAddress((void**)&p_qkv,  g_qkv);
    cudaGetSymbolAddress((void**)&p_attn, g_attn);
    cudaGetSymbolAddress((void**)&p_x2,   g_x2);
    cudaGetSymbolAddress((void**)&p_xn2,  g_xn2);
    cudaGetSymbolAddress((void**)&p_hid,  g_hid);

    static int attr_set = 0;
    if (!attr_set) {
        cudaFuncSetAttribute(attn_kernel,
            cudaFuncAttributeMaxDynamicSharedMemorySize,
            ATTN_SMEM_FLOATS * sizeof(float));
        cudaFuncSetAttribute(tgemm_kernel,
            cudaFuncAttributeMaxDynamicSharedMemorySize, GSMEM);
        attr_set = 1;
    }

    // 1) LN1 + window partition -> g_xw [9800, 768]
    ln_win_kernel<<<TOKW, 256>>>(x, g1, b1);

    // 2) QKV GEMM: [9800,768] @ [768,2304]
    {
        dim3 grid((3 * CDIM) / 128, (TOKW + 127) / 128);
        tgemm_kernel<<<grid, 256, GSMEM>>>(p_xw, w_qkv, b_qkv, nullptr, nullptr,
                                           p_qkv, TOKW, 3 * CDIM, CDIM, 0);
    }

    // 3) fused attention per (window, head)
    attn_kernel<<<dim3(NW, NHEAD), 256, ATTN_SMEM_FLOATS * sizeof(float)>>>(rel_h, rel_w);

    // 4) proj GEMM + window unpartition + residual -> g_x2 [8192, 768]
    {
        dim3 grid(CDIM / 128, (TOKW + 127) / 128);
        tgemm_kernel<<<grid, 256, GSMEM>>>(p_attn, w_proj, b_proj, nullptr, x,
                                           p_x2, TOKW, CDIM, CDIM, 3);
    }

    // 5) LN2 -> g_xn2
    ln2_kernel<<<TOKG, 256>>>(g2, b2);

    // 6) FC1 + GELU: [8192,768] @ [768,3072]
    {
        dim3 grid(MLPD / 128, TOKG / 128);
        tgemm_kernel<<<grid, 256, GSMEM>>>(p_xn2, w1, b1m, nullptr, nullptr,
                                           p_hid, TOKG, MLPD, CDIM, 1);
    }

    // 7) FC2 + residual: [8192,3072] @ [3072,768] -> out
    {
        dim3 grid(CDIM / 128, TOKG / 128);
        tgemm_kernel<<<grid, 256, GSMEM>>>(p_hid, w2, b2m, p_x2, nullptr,
                                           out, TOKG, CDIM, MLPD, 2);
    }
}

// round 7
// speedup vs baseline: 1.4859x; 1.2880x over previous
#include <cuda_runtime.h>
#include <cuda_fp16.h>
#include <math.h>
#include <stdint.h>

// ---------------- problem constants ----------------
#define BATCH   2
#define HT      64
#define WT      64
#define CDIM    768
#define WIN     14
#define NWIN1   5
#define NWINB   25
#define NW      50
#define HW      196
#define NHEAD   12
#define HD      64
#define MLPD    3072
#define TOKW    (NW*HW)        // 9800
#define TOKG    (BATCH*HT*WT)  // 8192
#define EPS     1e-5f

// ---------------- scratch ----------------
__device__ __half g_xw  [TOKW * CDIM];       // LN1 out (half, windowed)
__device__ float  g_qkv [TOKW * 3 * CDIM];   // qkv (float, attention reads)
__device__ __half g_attn[TOKW * CDIM];       // attention out (half)
__device__ float  g_x2  [TOKG * CDIM];       // x + attn (float)
__device__ __half g_xn2 [TOKG * CDIM];       // LN2 out (half)
__device__ __half g_hid [TOKG * MLPD];       // MLP hidden (half)
// transposed half weights [n][k]
__device__ __half g_wqkvT[3 * CDIM * CDIM];
__device__ __half g_wprojT[CDIM * CDIM];
__device__ __half g_w1T  [MLPD * CDIM];
__device__ __half g_w2T  [CDIM * MLPD];

// ---------------- helpers ----------------
__device__ __forceinline__ void win_map(int row, int& gidx, bool& valid) {
    int n  = row / HW, t = row % HW;
    int bb = n / NWINB, nw = n % NWINB;
    int wh = nw / NWIN1, ww = nw % NWIN1;
    int ii = t / WIN,    jj = t % WIN;
    int gh = wh * WIN + ii, gw = ww * WIN + jj;
    valid = (gh < HT) && (gw < WT);
    gidx  = (bb * HT + gh) * WT + gw;
}
__device__ __forceinline__ uint32_t smem_u32(const void* p) {
    return (uint32_t)__cvta_generic_to_shared(p);
}
__device__ __forceinline__ void cp16(uint32_t dst, const void* src, bool v) {
    int sz = v ? 16 : 0;
    asm volatile("cp.async.cg.shared.global [%0], [%1], 16, %2;\n"
                 :: "r"(dst), "l"(src), "r"(sz));
}
__device__ __forceinline__ void ldsm4(uint32_t& r0, uint32_t& r1,
                                      uint32_t& r2, uint32_t& r3, uint32_t a) {
    asm volatile("ldmatrix.sync.aligned.m8n8.x4.shared.b16 {%0,%1,%2,%3}, [%4];"
                 : "=r"(r0), "=r"(r1), "=r"(r2), "=r"(r3) : "r"(a));
}

// ---------------- weight transpose + fp32->fp16 ----------------
// src [K][N] float  ->  dst [N][K] half
__global__ __launch_bounds__(256) void f2hT_kernel(
    const float* __restrict__ src, __half* __restrict__ dst, int K, int N)
{
    __shared__ float t[32][33];
    int n0 = blockIdx.x * 32, k0 = blockIdx.y * 32;
    int tx = threadIdx.x, ty = threadIdx.y;   // 32 x 8
    #pragma unroll
    for (int i = 0; i < 32; i += 8)
        t[ty + i][tx] = src[(size_t)(k0 + ty + i) * N + n0 + tx];
    __syncthreads();
    #pragma unroll
    for (int i = 0; i < 32; i += 8)
        dst[(size_t)(n0 + ty + i) * K + k0 + tx] = __float2half_rn(t[tx][ty + i]);
}

// ---------------- LayerNorm kernels (half output) ----------------
__global__ __launch_bounds__(256) void ln_win_kernel(
    const float* __restrict__ x, const float* __restrict__ g,
    const float* __restrict__ b)
{
    int row = blockIdx.x;
    int tid = threadIdx.x;
    __half* orow = g_xw + (size_t)row * CDIM;

    int gidx; bool valid;
    win_map(row, gidx, valid);
    if (!valid) {
        for (int c = tid; c < CDIM; c += 256) orow[c] = __float2half_rn(0.f);
        return;
    }
    const float* xr = x + (size_t)gidx * CDIM;
    float v[3]; float s = 0.f, sq = 0.f;
    #pragma unroll
    for (int u = 0; u < 3; u++) {
        v[u] = xr[tid + u * 256];
        s += v[u]; sq += v[u] * v[u];
    }
    __shared__ float red[2][8];
    #pragma unroll
    for (int off = 16; off; off >>= 1) {
        s  += __shfl_xor_sync(~0u, s,  off);
        sq += __shfl_xor_sync(~0u, sq, off);
    }
    if ((tid & 31) == 0) { red[0][tid >> 5] = s; red[1][tid >> 5] = sq; }
    __syncthreads();
    if (tid < 32) {
        float a = (tid < 8) ? red[0][tid] : 0.f;
        float c = (tid < 8) ? red[1][tid] : 0.f;
        #pragma unroll
        for (int off = 4; off; off >>= 1) {
            a += __shfl_xor_sync(~0u, a, off);
            c += __shfl_xor_sync(~0u, c, off);
        }
        if (tid == 0) { red[0][0] = a; red[1][0] = c; }
    }
    __syncthreads();
    float mean = red[0][0] * (1.f / CDIM);
    float var  = red[1][0] * (1.f / CDIM) - mean * mean;
    float rstd = rsqrtf(var + EPS);
    #pragma unroll
    for (int u = 0; u < 3; u++) {
        int c = tid + u * 256;
        orow[c] = __float2half_rn((v[u] - mean) * rstd * g[c] + b[c]);
    }
}

__global__ __launch_bounds__(256) void ln2_kernel(
    const float* __restrict__ g, const float* __restrict__ b)
{
    int row = blockIdx.x;
    int tid = threadIdx.x;
    const float* xr = g_x2 + (size_t)row * CDIM;
    __half* orow = g_xn2 + (size_t)row * CDIM;
    float v[3]; float s = 0.f, sq = 0.f;
    #pragma unroll
    for (int u = 0; u < 3; u++) {
        v[u] = xr[tid + u * 256];
        s += v[u]; sq += v[u] * v[u];
    }
    __shared__ float red[2][8];
    #pragma unroll
    for (int off = 16; off; off >>= 1) {
        s  += __shfl_xor_sync(~0u, s,  off);
        sq += __shfl_xor_sync(~0u, sq, off);
    }
    if ((tid & 31) == 0) { red[0][tid >> 5] = s; red[1][tid >> 5] = sq; }
    __syncthreads();
    if (tid < 32) {
        float a = (tid < 8) ? red[0][tid] : 0.f;
        float c = (tid < 8) ? red[1][tid] : 0.f;
        #pragma unroll
        for (int off = 4; off; off >>= 1) {
            a += __shfl_xor_sync(~0u, a, off);
            c += __shfl_xor_sync(~0u, c, off);
        }
        if (tid == 0) { red[0][0] = a; red[1][0] = c; }
    }
    __syncthreads();
    float mean = red[0][0] * (1.f / CDIM);
    float var  = red[1][0] * (1.f / CDIM) - mean * mean;
    float rstd = rsqrtf(var + EPS);
    #pragma unroll
    for (int u = 0; u < 3; u++) {
        int c = tid + u * 256;
        orow[c] = __float2half_rn((v[u] - mean) * rstd * g[c] + b[c]);
    }
}

// ---------------- FP16 GEMM: both operands 3-stage cp.async, ldmatrix -------
// C[M,N] = A[M,K](half) @ Bt[N,K](half)^T + bias
// mode 0: float store (QKV)      1: exact GELU -> half store (FC1)
// mode 2: += res -> float (FC2)  3: window-unpartition + xin -> float (proj)
#define KTILE 32
#define AST   40                      // halfs per row (32 + 8 pad)
#define STG_H (128 * AST)             // halfs per stage
#define STG_B (STG_H * 2)             // bytes per stage (10240)
#define GSMEM (6 * STG_B)

__global__ __launch_bounds__(256, 2) void hgemm_kernel(
    const __half* __restrict__ A, const __half* __restrict__ Bt,
    const float* __restrict__ bias, const float* __restrict__ res,
    const float* __restrict__ xin, float* __restrict__ Cf,
    __half* __restrict__ Ch, int M, int N, int K, int mode)
{
    extern __shared__ __half shh[];
    __half* AsS = shh;                 // [3][128][AST]
    __half* BsS = shh + 3 * STG_H;     // [3][128][AST]

    int tid  = threadIdx.x;
    int warp = tid >> 5, lane = tid & 31;
    int wm = warp >> 2, wn = warp & 3;     // 2x4 warps, warp tile 64x32
    int gq = lane >> 2, tr = lane & 3;
    int bm = blockIdx.y * 128, bn = blockIdx.x * 128;

    // staging: row tid>>1, 16 halfs at (tid&1)*16
    int srow = tid >> 1;
    int scol = (tid & 1) * 16;
    int arow_g = bm + srow;
    bool aval = arow_g < M;
    const __half* Ag = A  + (size_t)(aval ? arow_g : (M - 1)) * K + scol;
    const __half* Bg = Bt + (size_t)(bn + srow) * K + scol;
    uint32_t as_st = smem_u32(AsS + srow * AST + scol);
    uint32_t bs_st = smem_u32(BsS + srow * AST + scol);

    uint32_t as_base = smem_u32(AsS);
    uint32_t bs_base = smem_u32(BsS);
    int fr = lane & 15;            // fragment row within 16
    int fc = (lane >> 4) * 8;      // fragment k-half select

    float acc[4][4][4];
    #pragma unroll
    for (int mi = 0; mi < 4; mi++)
        #pragma unroll
        for (int ni = 0; ni < 4; ni++)
            #pragma unroll
            for (int r = 0; r < 4; r++) acc[mi][ni][r] = 0.f;

    int T = K / KTILE;

    #define FILL(t, s) do {                                        \
        const __half* ag_ = Ag + (t) * KTILE;                      \
        uint32_t ad_ = as_st + (s) * STG_B;                        \
        cp16(ad_,      ag_,     aval);                             \
        cp16(ad_ + 16, ag_ + 8, aval);                             \
        const __half* bg_ = Bg + (t) * KTILE;                      \
        uint32_t bd_ = bs_st + (s) * STG_B;                        \
        cp16(bd_,      bg_,     true);                             \
        cp16(bd_ + 16, bg_ + 8, true);                             \
        asm volatile("cp.async.commit_group;\n");                  \
    } while (0)

    FILL(0, 0);
    FILL(1, 1);

    int s = 0;
    for (int t = 0; t < T; t++) {
        if (t + 1 < T) asm volatile("cp.async.wait_group 1;\n");
        else           asm volatile("cp.async.wait_group 0;\n");
        __syncthreads();
        if (t + 2 < T) {
            int sf = (s == 0) ? 2 : s - 1;   // (t+2) % 3
            FILL(t + 2, sf);
        }

        uint32_t ab = as_base + s * STG_B;
        uint32_t bb = bs_base + s * STG_B;
        #pragma unroll
        for (int kk = 0; kk < KTILE; kk += 16) {
            uint32_t af[4][4], bf[4][2];
            #pragma unroll
            for (int mi = 0; mi < 4; mi++) {
                uint32_t addr = ab +
                    (((wm * 64 + mi * 16 + fr) * AST) + kk + fc) * 2;
                ldsm4(af[mi][0], af[mi][1], af[mi][2], af[mi][3], addr);
            }
            #pragma unroll
            for (int nh = 0; nh < 2; nh++) {
                uint32_t addr = bb +
                    (((wn * 32 + nh * 16 + fr) * AST) + kk + fc) * 2;
                ldsm4(bf[2 * nh][0], bf[2 * nh + 1][0],
                      bf[2 * nh][1], bf[2 * nh + 1][1], addr);
            }
            #pragma unroll
            for (int mi = 0; mi < 4; mi++)
                #pragma unroll
                for (int ni = 0; ni < 4; ni++) {
                    asm volatile(
                        "mma.sync.aligned.m16n8k16.row.col.f32.f16.f16.f32 "
                        "{%0,%1,%2,%3}, {%4,%5,%6,%7}, {%8,%9}, {%0,%1,%2,%3};\n"
                        : "+f"(acc[mi][ni][0]), "+f"(acc[mi][ni][1]),
                          "+f"(acc[mi][ni][2]), "+f"(acc[mi][ni][3])
                        : "r"(af[mi][0]), "r"(af[mi][1]),
                          "r"(af[mi][2]), "r"(af[mi][3]),
                          "r"(bf[ni][0]), "r"(bf[ni][1]));
                }
        }
        s = (s == 2) ? 0 : s + 1;
    }
    #undef FILL

    // ---------------- epilogue ----------------
    #pragma unroll
    for (int mi = 0; mi < 4; mi++) {
        int rbase = bm + wm * 64 + mi * 16 + gq;
        #pragma unroll
        for (int h = 0; h < 2; h++) {
            int row = rbase + 8 * h;
            if (row >= M) continue;
            int gidx = 0; bool valid = true;
            if (mode == 3) {
                win_map(row, gidx, valid);
                if (!valid) continue;
            }
            #pragma unroll
            for (int ni = 0; ni < 4; ni++) {
                int col = bn + wn * 32 + ni * 8 + tr * 2;
                float v0 = acc[mi][ni][2 * h]     + bias[col];
                float v1 = acc[mi][ni][2 * h + 1] + bias[col + 1];
                if (mode == 1) {
                    v0 = 0.5f * v0 * (1.f + erff(v0 * 0.70710678118654752f));
                    v1 = 0.5f * v1 * (1.f + erff(v1 * 0.70710678118654752f));
                    *(__half2*)&Ch[(size_t)row * N + col] =
                        __floats2half2_rn(v0, v1);
                } else if (mode == 2) {
                    Cf[(size_t)row * N + col]     = v0 + res[(size_t)row * N + col];
                    Cf[(size_t)row * N + col + 1] = v1 + res[(size_t)row * N + col + 1];
                } else if (mode == 3) {
                    Cf[(size_t)gidx * N + col]     = v0 + xin[(size_t)gidx * N + col];
                    Cf[(size_t)gidx * N + col + 1] = v1 + xin[(size_t)gidx * N + col + 1];
                } else {
                    Cf[(size_t)row * N + col]     = v0;
                    Cf[(size_t)row * N + col + 1] = v1;
                }
            }
        }
    }
}

// ---------------- fused window attention (fp32 math, half output) -----------
#define KVS 68
#define ATTN_SMEM_FLOATS (HW*KVS*2 + 27*KVS*2 + 8*KVS + 8*28 + 8*200)

__global__ __launch_bounds__(256) void attn_kernel(
    const float* __restrict__ rel_h, const float* __restrict__ rel_w)
{
    extern __shared__ float sm[];
    float* ks = sm;                   // [196][68]
    float* vs = ks + HW * KVS;        // [196][68]
    float* rh = vs + HW * KVS;        // [27][68]
    float* rw = rh + 27 * KVS;        // [27][68]
    float* qs = rw + 27 * KVS;        // [8][68]
    float* bs = qs + 8 * KVS;         // [8][28]
    float* ps = bs + 8 * 28;          // [8][200]

    int w0   = blockIdx.x;
    int head = blockIdx.y;
    int tid  = threadIdx.x;
    int warp = tid >> 5, lane = tid & 31;

    const float* qkv_base = g_qkv + (size_t)w0 * HW * (3 * CDIM) + head * HD;
    for (int idx = tid; idx < HW * HD; idx += 256) {
        int kt = idx >> 6, d = idx & 63;
        const float* src = qkv_base + (size_t)kt * (3 * CDIM);
        ks[kt * KVS + d] = src[CDIM + d];
        vs[kt * KVS + d] = src[2 * CDIM + d];
    }
    for (int idx = tid; idx < 27 * HD; idx += 256) {
        int r = idx >> 6, d = idx & 63;
        rh[r * KVS + d] = rel_h[idx];
        rw[r * KVS + d] = rel_w[idx];
    }
    __syncthreads();

    int d0 = lane * 2;

    for (int r = warp; r < HW; r += 8) {
        size_t row = (size_t)w0 * HW + r;
        const float* qp = g_qkv + row * (3 * CDIM) + head * HD;
        qs[warp * KVS + lane]      = qp[lane];
        qs[warp * KVS + lane + 32] = qp[lane + 32];
        __syncwarp();

        int hq = r / WIN, wq = r % WIN;
        if (lane < 28) {
            const float* tab; int o;
            if (lane < 14) { tab = rh; o = (hq - lane + (WIN - 1)) * KVS; }
            else           { tab = rw; o = (wq - (lane - 14) + (WIN - 1)) * KVS; }
            float sacc = 0.f;
            #pragma unroll
            for (int d = 0; d < HD; d += 4) {
                float4 q4 = *(const float4*)&qs[warp * KVS + d];
                float4 t4 = *(const float4*)&tab[o + d];
                sacc += q4.x * t4.x + q4.y * t4.y + q4.z * t4.z + q4.w * t4.w;
            }
            bs[warp * 28 + lane] = sacc;
        }
        __syncwarp();

        float sc[7] = {0.f, 0.f, 0.f, 0.f, 0.f, 0.f, 0.f};
        int keyc[7];
        #pragma unroll
        for (int si = 0; si < 7; si++) {
            int key = lane + 32 * si;
            keyc[si] = key < HW ? key : HW - 1;
        }
        #pragma unroll 4
        for (int d = 0; d < HD; d += 4) {
            float4 q4 = *(const float4*)&qs[warp * KVS + d];
            #pragma unroll
            for (int si = 0; si < 7; si++) {
                float4 k4 = *(const float4*)&ks[keyc[si] * KVS + d];
                sc[si] += q4.x * k4.x + q4.y * k4.y + q4.z * k4.z + q4.w * k4.w;
            }
        }
        float mx = -1e30f;
        #pragma unroll
        for (int si = 0; si < 7; si++) {
            int key = lane + 32 * si;
            if (key < HW) {
                sc[si] = sc[si] * 0.125f
                       + bs[warp * 28 + key / WIN]
                       + bs[warp * 28 + 14 + key % WIN];
                mx = fmaxf(mx, sc[si]);
            } else sc[si] = -1e30f;
        }
        #pragma unroll
        for (int off = 16; off; off >>= 1)
            mx = fmaxf(mx, __shfl_xor_sync(~0u, mx, off));
        float sum = 0.f;
        #pragma unroll
        for (int si = 0; si < 7; si++) {
            int key = lane + 32 * si;
            if (key < HW) { float e = __expf(sc[si] - mx); sc[si] = e; sum += e; }
            else sc[si] = 0.f;
        }
        #pragma unroll
        for (int off = 16; off; off >>= 1)
            sum += __shfl_xor_sync(~0u, sum, off);
        float inv = 1.f / sum;
        #pragma unroll
        for (int si = 0; si < 7; si++) {
            int key = lane + 32 * si;
            if (key < HW) ps[warp * 200 + key] = sc[si] * inv;
        }
        __syncwarp();

        float o0 = 0.f, o1 = 0.f;
        #pragma unroll 4
        for (int k2 = 0; k2 < HW; k2 += 4) {
            float4 p4 = *(const float4*)&ps[warp * 200 + k2];
            float2 v0 = *(const float2*)&vs[(k2 + 0) * KVS + d0];
            float2 v1 = *(const float2*)&vs[(k2 + 1) * KVS + d0];
            float2 v2 = *(const float2*)&vs[(k2 + 2) * KVS + d0];
            float2 v3 = *(const float2*)&vs[(k2 + 3) * KVS + d0];
            o0 = fmaf(p4.x, v0.x, o0); o1 = fmaf(p4.x, v0.y, o1);
            o0 = fmaf(p4.y, v1.x, o0); o1 = fmaf(p4.y, v1.y, o1);
            o0 = fmaf(p4.z, v2.x, o0); o1 = fmaf(p4.z, v2.y, o1);
            o0 = fmaf(p4.w, v3.x, o0); o1 = fmaf(p4.w, v3.y, o1);
        }
        __half* op = g_attn + row * CDIM + head * HD;
        *(__half2*)&op[d0] = __floats2half2_rn(o0, o1);
        __syncwarp();
    }
}

// ---------------- launcher ----------------
extern "C" void kernel_launch(void* const* d_in, const int* in_sizes, int n_in,
                              void* d_out, int out_size)
{
    const float* x      = (const float*)d_in[0];
    const float* g1     = (const float*)d_in[1];
    const float* b1     = (const float*)d_in[2];
    const float* w_qkv  = (const float*)d_in[3];
    const float* b_qkv  = (const float*)d_in[4];
    const float* w_proj = (const float*)d_in[5];
    const float* b_proj = (const float*)d_in[6];
    const float* rel_h  = (const float*)d_in[7];
    const float* rel_w  = (const float*)d_in[8];
    const float* g2     = (const float*)d_in[9];
    const float* b2     = (const float*)d_in[10];
    const float* w1     = (const float*)d_in[11];
    const float* b1m    = (const float*)d_in[12];
    const float* w2     = (const float*)d_in[13];
    const float* b2m    = (const float*)d_in[14];
    float* out = (float*)d_out;

    __half *p_xw, *p_attn, *p_xn2, *p_hid;
    __half *p_wqkvT, *p_wprojT, *p_w1T, *p_w2T;
    float *p_qkv, *p_x2;
    cudaGetSymbolAddress((void**)&p_xw,    g_xw);
    cudaGetSymbolAddress((void**)&p_qkv,   g_qkv);
    cudaGetSymbolAddress((void**)&p_attn,  g_attn);
    cudaGetSymbolAddress((void**)&p_x2,    g_x2);
    cudaGetSymbolAddress((void**)&p_xn2,   g_xn2);
    cudaGetSymbolAddress((void**)&p_hid,   g_hid);
    cudaGetSymbolAddress((void**)&p_wqkvT, g_wqkvT);
    cudaGetSymbolAddress((void**)&p_wprojT,g_wprojT);
    cudaGetSymbolAddress((void**)&p_w1T,   g_w1T);
    cudaGetSymbolAddress((void**)&p_w2T,   g_w2T);

    static int attr_set = 0;
    if (!attr_set) {
        cudaFuncSetAttribute(attn_kernel,
            cudaFuncAttributeMaxDynamicSharedMemorySize,
            ATTN_SMEM_FLOATS * sizeof(float));
        cudaFuncSetAttribute(hgemm_kernel,
            cudaFuncAttributeMaxDynamicSharedMemorySize, GSMEM);
        attr_set = 1;
    }

    dim3 tb(32, 8);
    // 0) weight transpose+convert: [K][N] f32 -> [N][K] f16
    f2hT_kernel<<<dim3((3 * CDIM) / 32, CDIM / 32), tb>>>(w_qkv,  p_wqkvT, CDIM, 3 * CDIM);
    f2hT_kernel<<<dim3(CDIM / 32, CDIM / 32),       tb>>>(w_proj, p_wprojT, CDIM, CDIM);
    f2hT_kernel<<<dim3(MLPD / 32, CDIM / 32),       tb>>>(w1,     p_w1T, CDIM, MLPD);
    f2hT_kernel<<<dim3(CDIM / 32, MLPD / 32),       tb>>>(w2,     p_w2T, MLPD, CDIM);

    // 1) LN1 + window partition -> g_xw (half)
    ln_win_kernel<<<TOKW, 256>>>(x, g1, b1);

    // 2) QKV GEMM -> g_qkv (float)
    {
        dim3 grid((3 * CDIM) / 128, (TOKW + 127) / 128);
        hgemm_kernel<<<grid, 256, GSMEM>>>(p_xw, p_wqkvT, b_qkv, nullptr, nullptr,
                                           p_qkv, nullptr, TOKW, 3 * CDIM, CDIM, 0);
    }

    // 3) fused attention -> g_attn (half)
    attn_kernel<<<dim3(NW, NHEAD), 256, ATTN_SMEM_FLOATS * sizeof(float)>>>(rel_h, rel_w);

    // 4) proj GEMM + unpartition + residual -> g_x2 (float)
    {
        dim3 grid(CDIM / 128, (TOKW + 127) / 128);
        hgemm_kernel<<<grid, 256, GSMEM>>>(p_attn, p_wprojT, b_proj, nullptr, x,
                                           p_x2, nullptr, TOKW, CDIM, CDIM, 3);
    }

    // 5) LN2 -> g_xn2 (half)
    ln2_kernel<<<TOKG, 256>>>(g2, b2);

    // 6) FC1 + GELU -> g_hid (half)
    {
        dim3 grid(MLPD / 128, TOKG / 128);
        hgemm_kernel<<<grid, 256, GSMEM>>>(p_xn2, p_w1T, b1m, nullptr, nullptr,
                                           nullptr, p_hid, TOKG, MLPD, CDIM, 1);
    }

    // 7) FC2 + residual -> out (float)
    {
        dim3 grid(CDIM / 128, TOKG / 128);
        hgemm_kernel<<<grid, 256, GSMEM>>>(p_hid, p_w2T, b2m, p_x2, nullptr,
                                           out, nullptr, TOKG, CDIM, MLPD, 2);
    }
}

// round 8
// speedup vs baseline: 1.8020x; 1.2128x over previous
#include <cuda_runtime.h>
#include <cuda_fp16.h>
#include <math.h>
#include <stdint.h>

// ---------------- problem constants ----------------
#define BATCH   2
#define HT      64
#define WT      64
#define CDIM    768
#define WIN     14
#define NWIN1   5
#define NWINB   25
#define NW      50
#define HW      196
#define NHEAD   12
#define HD      64
#define MLPD    3072
#define TOKW    (NW*HW)        // 9800
#define TOKG    (BATCH*HT*WT)  // 8192
#define EPS     1e-5f

// ---------------- scratch ----------------
__device__ __half g_xw  [TOKW * CDIM];       // LN1 out (half, windowed)
__device__ __half g_qkv [TOKW * 3 * CDIM];   // qkv (half)
__device__ __half g_attn[TOKW * CDIM];       // attention out (half)
__device__ float  g_x2  [TOKG * CDIM];       // x + attn (float)
__device__ __half g_xn2 [TOKG * CDIM];       // LN2 out (half)
__device__ __half g_hid [TOKG * MLPD];       // MLP hidden (half)
// transposed half weights [n][k]
__device__ __half g_wqkvT[3 * CDIM * CDIM];
__device__ __half g_wprojT[CDIM * CDIM];
__device__ __half g_w1T  [MLPD * CDIM];
__device__ __half g_w2T  [CDIM * MLPD];

// ---------------- helpers ----------------
__device__ __forceinline__ void win_map(int row, int& gidx, bool& valid) {
    int n  = row / HW, t = row % HW;
    int bb = n / NWINB, nw = n % NWINB;
    int wh = nw / NWIN1, ww = nw % NWIN1;
    int ii = t / WIN,    jj = t % WIN;
    int gh = wh * WIN + ii, gw = ww * WIN + jj;
    valid = (gh < HT) && (gw < WT);
    gidx  = (bb * HT + gh) * WT + gw;
}
__device__ __forceinline__ uint32_t smem_u32(const void* p) {
    return (uint32_t)__cvta_generic_to_shared(p);
}
__device__ __forceinline__ void cp16(uint32_t dst, const void* src, bool v) {
    int sz = v ? 16 : 0;
    asm volatile("cp.async.cg.shared.global [%0], [%1], 16, %2;\n"
                 :: "r"(dst), "l"(src), "r"(sz));
}
__device__ __forceinline__ void ldsm4(uint32_t& r0, uint32_t& r1,
                                      uint32_t& r2, uint32_t& r3, uint32_t a) {
    asm volatile("ldmatrix.sync.aligned.m8n8.x4.shared.b16 {%0,%1,%2,%3}, [%4];"
                 : "=r"(r0), "=r"(r1), "=r"(r2), "=r"(r3) : "r"(a));
}
__device__ __forceinline__ void mma16816(float* c, const uint32_t* a,
                                         const uint32_t* b) {
    asm volatile(
        "mma.sync.aligned.m16n8k16.row.col.f32.f16.f16.f32 "
        "{%0,%1,%2,%3}, {%4,%5,%6,%7}, {%8,%9}, {%0,%1,%2,%3};\n"
        : "+f"(c[0]), "+f"(c[1]), "+f"(c[2]), "+f"(c[3])
        : "r"(a[0]), "r"(a[1]), "r"(a[2]), "r"(a[3]),
          "r"(b[0]), "r"(b[1]));
}

// ---------------- weight transpose + fp32->fp16 ----------------
__global__ __launch_bounds__(256) void f2hT_kernel(
    const float* __restrict__ src, __half* __restrict__ dst, int K, int N)
{
    __shared__ float t[32][33];
    int n0 = blockIdx.x * 32, k0 = blockIdx.y * 32;
    int tx = threadIdx.x, ty = threadIdx.y;   // 32 x 8
    #pragma unroll
    for (int i = 0; i < 32; i += 8)
        t[ty + i][tx] = src[(size_t)(k0 + ty + i) * N + n0 + tx];
    __syncthreads();
    #pragma unroll
    for (int i = 0; i < 32; i += 8)
        dst[(size_t)(n0 + ty + i) * K + k0 + tx] = __float2half_rn(t[tx][ty + i]);
}

// ---------------- LayerNorm kernels (half output) ----------------
__global__ __launch_bounds__(256) void ln_win_kernel(
    const float* __restrict__ x, const float* __restrict__ g,
    const float* __restrict__ b)
{
    int row = blockIdx.x;
    int tid = threadIdx.x;
    __half* orow = g_xw + (size_t)row * CDIM;

    int gidx; bool valid;
    win_map(row, gidx, valid);
    if (!valid) {
        for (int c = tid; c < CDIM; c += 256) orow[c] = __float2half_rn(0.f);
        return;
    }
    const float* xr = x + (size_t)gidx * CDIM;
    float v[3]; float s = 0.f, sq = 0.f;
    #pragma unroll
    for (int u = 0; u < 3; u++) {
        v[u] = xr[tid + u * 256];
        s += v[u]; sq += v[u] * v[u];
    }
    __shared__ float red[2][8];
    #pragma unroll
    for (int off = 16; off; off >>= 1) {
        s  += __shfl_xor_sync(~0u, s,  off);
        sq += __shfl_xor_sync(~0u, sq, off);
    }
    if ((tid & 31) == 0) { red[0][tid >> 5] = s; red[1][tid >> 5] = sq; }
    __syncthreads();
    if (tid < 32) {
        float a = (tid < 8) ? red[0][tid] : 0.f;
        float c = (tid < 8) ? red[1][tid] : 0.f;
        #pragma unroll
        for (int off = 4; off; off >>= 1) {
            a += __shfl_xor_sync(~0u, a, off);
            c += __shfl_xor_sync(~0u, c, off);
        }
        if (tid == 0) { red[0][0] = a; red[1][0] = c; }
    }
    __syncthreads();
    float mean = red[0][0] * (1.f / CDIM);
    float var  = red[1][0] * (1.f / CDIM) - mean * mean;
    float rstd = rsqrtf(var + EPS);
    #pragma unroll
    for (int u = 0; u < 3; u++) {
        int c = tid + u * 256;
        orow[c] = __float2half_rn((v[u] - mean) * rstd * g[c] + b[c]);
    }
}

__global__ __launch_bounds__(256) void ln2_kernel(
    const float* __restrict__ g, const float* __restrict__ b)
{
    int row = blockIdx.x;
    int tid = threadIdx.x;
    const float* xr = g_x2 + (size_t)row * CDIM;
    __half* orow = g_xn2 + (size_t)row * CDIM;
    float v[3]; float s = 0.f, sq = 0.f;
    #pragma unroll
    for (int u = 0; u < 3; u++) {
        v[u] = xr[tid + u * 256];
        s += v[u]; sq += v[u] * v[u];
    }
    __shared__ float red[2][8];
    #pragma unroll
    for (int off = 16; off; off >>= 1) {
        s  += __shfl_xor_sync(~0u, s,  off);
        sq += __shfl_xor_sync(~0u, sq, off);
    }
    if ((tid & 31) == 0) { red[0][tid >> 5] = s; red[1][tid >> 5] = sq; }
    __syncthreads();
    if (tid < 32) {
        float a = (tid < 8) ? red[0][tid] : 0.f;
        float c = (tid < 8) ? red[1][tid] : 0.f;
        #pragma unroll
        for (int off = 4; off; off >>= 1) {
            a += __shfl_xor_sync(~0u, a, off);
            c += __shfl_xor_sync(~0u, c, off);
        }
        if (tid == 0) { red[0][0] = a; red[1][0] = c; }
    }
    __syncthreads();
    float mean = red[0][0] * (1.f / CDIM);
    float var  = red[1][0] * (1.f / CDIM) - mean * mean;
    float rstd = rsqrtf(var + EPS);
    #pragma unroll
    for (int u = 0; u < 3; u++) {
        int c = tid + u * 256;
        orow[c] = __float2half_rn((v[u] - mean) * rstd * g[c] + b[c]);
    }
}

// ---------------- FP16 GEMM (unchanged R7 winner, mode0 -> half out) --------
// mode 0: half store (QKV)       1: exact GELU -> half store (FC1)
// mode 2: += res -> float (FC2)  3: window-unpartition + xin -> float (proj)
#define KTILE 32
#define AST   40
#define STG_H (128 * AST)
#define STG_B (STG_H * 2)
#define GSMEM (6 * STG_B)

__global__ __launch_bounds__(256, 2) void hgemm_kernel(
    const __half* __restrict__ A, const __half* __restrict__ Bt,
    const float* __restrict__ bias, const float* __restrict__ res,
    const float* __restrict__ xin, float* __restrict__ Cf,
    __half* __restrict__ Ch, int M, int N, int K, int mode)
{
    extern __shared__ __half shh[];
    __half* AsS = shh;
    __half* BsS = shh + 3 * STG_H;

    int tid  = threadIdx.x;
    int warp = tid >> 5, lane = tid & 31;
    int wm = warp >> 2, wn = warp & 3;
    int gq = lane >> 2, tr = lane & 3;
    int bm = blockIdx.y * 128, bn = blockIdx.x * 128;

    int srow = tid >> 1;
    int scol = (tid & 1) * 16;
    int arow_g = bm + srow;
    bool aval = arow_g < M;
    const __half* Ag = A  + (size_t)(aval ? arow_g : (M - 1)) * K + scol;
    const __half* Bg = Bt + (size_t)(bn + srow) * K + scol;
    uint32_t as_st = smem_u32(AsS + srow * AST + scol);
    uint32_t bs_st = smem_u32(BsS + srow * AST + scol);

    uint32_t as_base = smem_u32(AsS);
    uint32_t bs_base = smem_u32(BsS);
    int fr = lane & 15;
    int fc = (lane >> 4) * 8;

    float acc[4][4][4];
    #pragma unroll
    for (int mi = 0; mi < 4; mi++)
        #pragma unroll
        for (int ni = 0; ni < 4; ni++)
            #pragma unroll
            for (int r = 0; r < 4; r++) acc[mi][ni][r] = 0.f;

    int T = K / KTILE;

    #define FILL(t, s) do {                                        \
        const __half* ag_ = Ag + (t) * KTILE;                      \
        uint32_t ad_ = as_st + (s) * STG_B;                        \
        cp16(ad_,      ag_,     aval);                             \
        cp16(ad_ + 16, ag_ + 8, aval);                             \
        const __half* bg_ = Bg + (t) * KTILE;                      \
        uint32_t bd_ = bs_st + (s) * STG_B;                        \
        cp16(bd_,      bg_,     true);                             \
        cp16(bd_ + 16, bg_ + 8, true);                             \
        asm volatile("cp.async.commit_group;\n");                  \
    } while (0)

    FILL(0, 0);
    FILL(1, 1);

    int s = 0;
    for (int t = 0; t < T; t++) {
        if (t + 1 < T) asm volatile("cp.async.wait_group 1;\n");
        else           asm volatile("cp.async.wait_group 0;\n");
        __syncthreads();
        if (t + 2 < T) {
            int sf = (s == 0) ? 2 : s - 1;
            FILL(t + 2, sf);
        }

        uint32_t ab = as_base + s * STG_B;
        uint32_t bb = bs_base + s * STG_B;
        #pragma unroll
        for (int kk = 0; kk < KTILE; kk += 16) {
            uint32_t af[4][4], bf[4][2];
            #pragma unroll
            for (int mi = 0; mi < 4; mi++) {
                uint32_t addr = ab +
                    (((wm * 64 + mi * 16 + fr) * AST) + kk + fc) * 2;
                ldsm4(af[mi][0], af[mi][1], af[mi][2], af[mi][3], addr);
            }
            #pragma unroll
            for (int nh = 0; nh < 2; nh++) {
                uint32_t addr = bb +
                    (((wn * 32 + nh * 16 + fr) * AST) + kk + fc) * 2;
                ldsm4(bf[2 * nh][0], bf[2 * nh + 1][0],
                      bf[2 * nh][1], bf[2 * nh + 1][1], addr);
            }
            #pragma unroll
            for (int mi = 0; mi < 4; mi++)
                #pragma unroll
                for (int ni = 0; ni < 4; ni++)
                    mma16816(acc[mi][ni], af[mi], bf[ni]);
        }
        s = (s == 2) ? 0 : s + 1;
    }
    #undef FILL

    #pragma unroll
    for (int mi = 0; mi < 4; mi++) {
        int rbase = bm + wm * 64 + mi * 16 + gq;
        #pragma unroll
        for (int h = 0; h < 2; h++) {
            int row = rbase + 8 * h;
            if (row >= M) continue;
            int gidx = 0; bool valid = true;
            if (mode == 3) {
                win_map(row, gidx, valid);
                if (!valid) continue;
            }
            #pragma unroll
            for (int ni = 0; ni < 4; ni++) {
                int col = bn + wn * 32 + ni * 8 + tr * 2;
                float v0 = acc[mi][ni][2 * h]     + bias[col];
                float v1 = acc[mi][ni][2 * h + 1] + bias[col + 1];
                if (mode == 0) {
                    *(__half2*)&Ch[(size_t)row * N + col] =
                        __floats2half2_rn(v0, v1);
                } else if (mode == 1) {
                    v0 = 0.5f * v0 * (1.f + erff(v0 * 0.70710678118654752f));
                    v1 = 0.5f * v1 * (1.f + erff(v1 * 0.70710678118654752f));
                    *(__half2*)&Ch[(size_t)row * N + col] =
                        __floats2half2_rn(v0, v1);
                } else if (mode == 2) {
                    Cf[(size_t)row * N + col]     = v0 + res[(size_t)row * N + col];
                    Cf[(size_t)row * N + col + 1] = v1 + res[(size_t)row * N + col + 1];
                } else {
                    Cf[(size_t)gidx * N + col]     = v0 + xin[(size_t)gidx * N + col];
                    Cf[(size_t)gidx * N + col + 1] = v1 + xin[(size_t)gidx * N + col + 1];
                }
            }
        }
    }
}

// ---------------- tensor-core window attention ----------------
// one block per (window, head); 256 threads = 8 warps.
#define QKS   72     // Q/K smem stride (halfs); 36 words == 4 mod 8
#define VPS   216    // V^T / P smem stride (halfs); 108 words == 4 mod 8
#define SSX   212    // S smem stride (floats)
// float section: S[64][212], bh[196*14], bw[196*14], rh[27*64], rw[27*64]
#define F_S   0
#define F_BH  (64 * SSX)
#define F_BW  (F_BH + HW * WIN)
#define F_RH  (F_BW + HW * WIN)
#define F_RW  (F_RH + 27 * HD)
#define F_TOT (F_RW + 27 * HD)
// half section
#define H_Q   0
#define H_K   (HW * QKS)
#define H_VT  (H_K + HW * QKS)
#define H_P   (H_VT + HD * VPS)
#define H_TOT (H_P + 64 * VPS)
#define ATTN_SMEM_BYTES (F_TOT * 4 + H_TOT * 2)

__global__ __launch_bounds__(256, 1) void attn_kernel(
    const float* __restrict__ rel_h, const float* __restrict__ rel_w)
{
    extern __shared__ float smf[];
    float* Ss = smf + F_S;
    float* bh = smf + F_BH;
    float* bw = smf + F_BW;
    float* rhs = smf + F_RH;
    float* rws = smf + F_RW;
    __half* hbase = (__half*)(smf + F_TOT);
    __half* qs  = hbase + H_Q;
    __half* kss = hbase + H_K;
    __half* vts = hbase + H_VT;
    __half* ps  = hbase + H_P;

    int w0   = blockIdx.x;
    int head = blockIdx.y;
    int tid  = threadIdx.x;
    int warp = tid >> 5, lane = tid & 31;
    int gq = lane >> 2, tr = lane & 3;
    int fr = lane & 15;
    int fc = (lane >> 4) * 8;

    uint32_t qs_b  = smem_u32(qs);
    uint32_t ks_b  = smem_u32(kss);
    uint32_t vt_b  = smem_u32(vts);
    uint32_t ps_b  = smem_u32(ps);

    // ---- stage Q,K (row-major) ----
    const __half* qkvb = g_qkv + (size_t)w0 * HW * (3 * CDIM) + head * HD;
    for (int idx = tid; idx < HW * 16; idx += 256) {
        int row = idx >> 4, d = (idx & 15) * 4;
        const __half* src = qkvb + (size_t)row * (3 * CDIM) + d;
        *(uint2*)&qs [row * QKS + d] = *(const uint2*)(src);
        *(uint2*)&kss[row * QKS + d] = *(const uint2*)(src + CDIM);
    }
    // ---- stage V transposed: vts[d][key] ----
    for (int idx = tid; idx < HW * HD; idx += 256) {
        int key = idx >> 6, d = idx & 63;
        vts[d * VPS + key] = qkvb[(size_t)key * (3 * CDIM) + 2 * CDIM + d];
    }
    for (int idx = tid; idx < HD * 12; idx += 256) {
        int d = idx / 12;
        vts[d * VPS + HW + idx % 12] = __float2half_rn(0.f);
    }
    // ---- rel tables ----
    for (int idx = tid; idx < 27 * HD; idx += 256) {
        rhs[idx] = rel_h[idx];
        rws[idx] = rel_w[idx];
    }
    __syncthreads();

    // ---- bias tables: bh[q][kh], bw[q][kw] ----
    for (int j = tid; j < HW * 28; j += 256) {
        int q = j / 28, wch = j % 28;
        int hq = q / WIN, wq = q % WIN;
        const float* tab;
        int o;
        if (wch < 14) { tab = rhs; o = (hq - wch + (WIN - 1)) * HD; }
        else          { tab = rws; o = (wq - (wch - 14) + (WIN - 1)) * HD; }
        float acc = 0.f;
        #pragma unroll
        for (int d = 0; d < HD; d += 4) {
            uint2 hv = *(const uint2*)&qs[q * QKS + d];
            float2 f0 = __half22float2(*(__half2*)&hv.x);
            float2 f1 = __half22float2(*(__half2*)&hv.y);
            float4 t4 = *(const float4*)&tab[o + d];
            acc += f0.x * t4.x + f0.y * t4.y + f1.x * t4.z + f1.y * t4.w;
        }
        if (wch < 14) bh[q * WIN + wch] = acc;
        else          bw[q * WIN + wch - 14] = acc;
    }
    __syncthreads();

    int stripe = warp >> 1, nh = warp & 1;
    int ngr   = nh ? 6 : 7;         // 16-key groups (nh0: keys 0..111, nh1: 112..207)
    int nbase = nh ? 112 : 0;

    for (int c = 0; c < 4; c++) {
        int q0 = c * 64;
        int rows = (HW - q0 < 64) ? (HW - q0) : 64;
        int nstripes = (rows + 15) >> 4;

        // ---- scores: S[rows][208] = Q * K^T ----
        if (stripe < nstripes) {
            int mrow = q0 + stripe * 16;
            float sacc[7][2][4];
            #pragma unroll
            for (int g = 0; g < 7; g++)
                #pragma unroll
                for (int u = 0; u < 2; u++)
                    #pragma unroll
                    for (int r = 0; r < 4; r++) sacc[g][u][r] = 0.f;

            #pragma unroll
            for (int kk = 0; kk < HD; kk += 16) {
                uint32_t af[4];
                int ar = mrow + fr; if (ar > HW - 1) ar = HW - 1;
                ldsm4(af[0], af[1], af[2], af[3],
                      qs_b + (ar * QKS + kk + fc) * 2);
                for (int g = 0; g < ngr; g++) {
                    int br = nbase + g * 16 + fr; if (br > HW - 1) br = HW - 1;
                    uint32_t bf0[2], bf1[2];
                    ldsm4(bf0[0], bf1[0], bf0[1], bf1[1],
                          ks_b + (br * QKS + kk + fc) * 2);
                    mma16816(sacc[g][0], af, bf0);
                    mma16816(sacc[g][1], af, bf1);
                }
            }
            for (int g = 0; g < ngr; g++) {
                #pragma unroll
                for (int u = 0; u < 2; u++) {
                    int col = nbase + g * 16 + u * 8 + tr * 2;
                    int r0 = stripe * 16 + gq;
                    *(float2*)&Ss[r0 * SSX + col] =
                        make_float2(sacc[g][u][0], sacc[g][u][1]);
                    *(float2*)&Ss[(r0 + 8) * SSX + col] =
                        make_float2(sacc[g][u][2], sacc[g][u][3]);
                }
            }
        }
        __syncthreads();

        // ---- softmax rows, write P (half) ----
        for (int r = warp; r < rows; r += 8) {
            int q = q0 + r;
            float v[7];
            float mx = -1e30f;
            #pragma unroll
            for (int i = 0; i < 7; i++) {
                int col = lane + 32 * i;
                if (col < HW) {
                    float sv = Ss[r * SSX + col] * 0.125f
                             + bh[q * WIN + col / WIN]
                             + bw[q * WIN + col % WIN];
                    v[i] = sv;
                    mx = fmaxf(mx, sv);
                } else v[i] = -1e30f;
            }
            #pragma unroll
            for (int off = 16; off; off >>= 1)
                mx = fmaxf(mx, __shfl_xor_sync(~0u, mx, off));
            float sum = 0.f;
            #pragma unroll
            for (int i = 0; i < 7; i++) {
                int col = lane + 32 * i;
                if (col < HW) { float e = __expf(v[i] - mx); v[i] = e; sum += e; }
                else v[i] = 0.f;
            }
            #pragma unroll
            for (int off = 16; off; off >>= 1)
                sum += __shfl_xor_sync(~0u, sum, off);
            float inv = 1.f / sum;
            #pragma unroll
            for (int i = 0; i < 7; i++) {
                int col = lane + 32 * i;
                if (col < HW)       ps[r * VPS + col] = __float2half_rn(v[i] * inv);
                else if (col < 208) ps[r * VPS + col] = __float2half_rn(0.f);
            }
        }
        __syncthreads();

        // ---- PV: out[rows][64] = P * V ----
        if (stripe < nstripes) {
            int d0b = nh * 32;
            float oacc[4][4];
            #pragma unroll
            for (int ni = 0; ni < 4; ni++)
                #pragma unroll
                for (int r = 0; r < 4; r++) oacc[ni][r] = 0.f;

            for (int kk = 0; kk < 208; kk += 16) {
                uint32_t af[4];
                ldsm4(af[0], af[1], af[2], af[3],
                      ps_b + ((stripe * 16 + fr) * VPS + kk + fc) * 2);
                #pragma unroll
                for (int g = 0; g < 2; g++) {
                    uint32_t bf0[2], bf1[2];
                    ldsm4(bf0[0], bf1[0], bf0[1], bf1[1],
                          vt_b + ((d0b + g * 16 + fr) * VPS + kk + fc) * 2);
                    mma16816(oacc[2 * g],     af, bf0);
                    mma16816(oacc[2 * g + 1], af, bf1);
                }
            }
            #pragma unroll
            for (int ni = 0; ni < 4; ni++) {
                int col = head * HD + d0b + ni * 8 + tr * 2;
                #pragma unroll
                for (int h = 0; h < 2; h++) {
                    int grow = q0 + stripe * 16 + gq + 8 * h;
                    if (grow < HW) {
                        __half* op = g_attn + ((size_t)w0 * HW + grow) * CDIM + col;
                        *(__half2*)op = __floats2half2_rn(oacc[ni][2 * h],
                                                          oacc[ni][2 * h + 1]);
                    }
                }
            }
        }
        __syncthreads();
    }
}

// ---------------- launcher ----------------
extern "C" void kernel_launch(void* const* d_in, const int* in_sizes, int n_in,
                              void* d_out, int out_size)
{
    const float* x      = (const float*)d_in[0];
    const float* g1     = (const float*)d_in[1];
    const float* b1     = (const float*)d_in[2];
    const float* w_qkv  = (const float*)d_in[3];
    const float* b_qkv  = (const float*)d_in[4];
    const float* w_proj = (const float*)d_in[5];
    const float* b_proj = (const float*)d_in[6];
    const float* rel_h  = (const float*)d_in[7];
    const float* rel_w  = (const float*)d_in[8];
    const float* g2     = (const float*)d_in[9];
    const float* b2     = (const float*)d_in[10];
    const float* w1     = (const float*)d_in[11];
    const float* b1m    = (const float*)d_in[12];
    const float* w2     = (const float*)d_in[13];
    const float* b2m    = (const float*)d_in[14];
    float* out = (float*)d_out;

    __half *p_xw, *p_qkv, *p_attn, *p_xn2, *p_hid;
    __half *p_wqkvT, *p_wprojT, *p_w1T, *p_w2T;
    float *p_x2;
    cudaGetSymbolAddress((void**)&p_xw,    g_xw);
    cudaGetSymbolAddress((void**)&p_qkv,   g_qkv);
    cudaGetSymbolAddress((void**)&p_attn,  g_attn);
    cudaGetSymbolAddress((void**)&p_x2,    g_x2);
    cudaGetSymbolAddress((void**)&p_xn2,   g_xn2);
    cudaGetSymbolAddress((void**)&p_hid,   g_hid);
    cudaGetSymbolAddress((void**)&p_wqkvT, g_wqkvT);
    cudaGetSymbolAddress((void**)&p_wprojT,g_wprojT);
    cudaGetSymbolAddress((void**)&p_w1T,   g_w1T);
    cudaGetSymbolAddress((void**)&p_w2T,   g_w2T);

    static int attr_set = 0;
    if (!attr_set) {
        cudaFuncSetAttribute(attn_kernel,
            cudaFuncAttributeMaxDynamicSharedMemorySize, ATTN_SMEM_BYTES);
        cudaFuncSetAttribute(hgemm_kernel,
            cudaFuncAttributeMaxDynamicSharedMemorySize, GSMEM);
        attr_set = 1;
    }

    dim3 tb(32, 8);
    f2hT_kernel<<<dim3((3 * CDIM) / 32, CDIM / 32), tb>>>(w_qkv,  p_wqkvT, CDIM, 3 * CDIM);
    f2hT_kernel<<<dim3(CDIM / 32, CDIM / 32),       tb>>>(w_proj, p_wprojT, CDIM, CDIM);
    f2hT_kernel<<<dim3(MLPD / 32, CDIM / 32),       tb>>>(w1,     p_w1T, CDIM, MLPD);
    f2hT_kernel<<<dim3(CDIM / 32, MLPD / 32),       tb>>>(w2,     p_w2T, MLPD, CDIM);

    // 1) LN1 + window partition -> g_xw (half)
    ln_win_kernel<<<TOKW, 256>>>(x, g1, b1);

    // 2) QKV GEMM -> g_qkv (half)
    {
        dim3 grid((3 * CDIM) / 128, (TOKW + 127) / 128);
        hgemm_kernel<<<grid, 256, GSMEM>>>(p_xw, p_wqkvT, b_qkv, nullptr, nullptr,
                                           nullptr, p_qkv, TOKW, 3 * CDIM, CDIM, 0);
    }

    // 3) tensor-core attention -> g_attn (half)
    attn_kernel<<<dim3(NW, NHEAD), 256, ATTN_SMEM_BYTES>>>(rel_h, rel_w);

    // 4) proj GEMM + unpartition + residual -> g_x2 (float)
    {
        dim3 grid(CDIM / 128, (TOKW + 127) / 128);
        hgemm_kernel<<<grid, 256, GSMEM>>>(p_attn, p_wprojT, b_proj, nullptr, x,
                                           p_x2, nullptr, TOKW, CDIM, CDIM, 3);
    }

    // 5) LN2 -> g_xn2 (half)
    ln2_kernel<<<TOKG, 256>>>(g2, b2);

    // 6) FC1 + GELU -> g_hid (half)
    {
        dim3 grid(MLPD / 128, TOKG / 128);
        hgemm_kernel<<<grid, 256, GSMEM>>>(p_xn2, p_w1T, b1m, nullptr, nullptr,
                                           nullptr, p_hid, TOKG, MLPD, CDIM, 1);
    }

    // 7) FC2 + residual -> out (float)
    {
        dim3 grid(CDIM / 128, TOKG / 128);
        hgemm_kernel<<<grid, 256, GSMEM>>>(p_hid, p_w2T, b2m, p_x2, nullptr,
                                           out, nullptr, TOKG, CDIM, MLPD, 2);
    }
}